// round 1
// baseline (speedup 1.0000x reference)
#include <cuda_runtime.h>
#include <cuda_bf16.h>
#include <stdint.h>

// Problem constants (fixed-shape problem; runtime sizes used for loop bounds)
#define NMAX 100000
#define EMAX 1600000
#define HDIM 128
#define FDIM 128
#define CDIM 64
#define GMAX 512

// ---------------- scratch (__device__ globals; no runtime allocation) ------
__device__ float g_h1[(size_t)NMAX * HDIM];   // 51.2 MB  node features after fused pre GEMM
__device__ float g_dinv[NMAX];
__device__ int   g_cnt[NMAX];                 // in-degree (edges only)
__device__ int   g_rowptr[NMAX];              // exclusive scan of g_cnt
__device__ int   g_fill[NMAX];
__device__ int   g_csr[EMAX];                 // src ids grouped by dst
__device__ int   g_blocksums[256];
__device__ float g_readout[GMAX * HDIM];
__device__ float g_Wf[FDIM * HDIM];           // W_pre @ W_conv
__device__ float g_bf[HDIM];                  // b_pre @ W_conv
__device__ int   g_is64;

// ---------------- index dtype detection -----------------------------------
// If edge_index is int64 (little-endian, values < 2^31), every odd 32-bit
// word of the buffer is 0. If int32, odd words are random indices.
__global__ void k_detect(const int* __restrict__ p) {
    if (threadIdx.x == 0) {
        int acc = 0;
        for (int i = 1; i < 256; i += 2) acc |= p[i];
        g_is64 = (acc == 0) ? 1 : 0;
    }
}

__device__ __forceinline__ int ld_idx(const void* p, long long i, bool w64) {
    return w64 ? (int)((const long long*)p)[i] : ((const int*)p)[i];
}

// ---------------- zero scratch ---------------------------------------------
__global__ void k_zero(int N, int G) {
    int i = blockIdx.x * blockDim.x + threadIdx.x;
    int total = 2 * N + G * HDIM;
    if (i >= total) return;
    if (i < N)            g_cnt[i] = 0;
    else if (i < 2 * N)   g_fill[i - N] = 0;
    else                  g_readout[i - 2 * N] = 0.f;
}

// ---------------- fuse W_pre @ W_conv --------------------------------------
__global__ void k_fuse(const float* __restrict__ Wpre, const float* __restrict__ bpre,
                       const float* __restrict__ Wconv) {
    int j = threadIdx.x;           // 0..127
    int i = blockIdx.x;            // 0..128 (128 = bias row)
    if (i < FDIM) {
        float a = 0.f;
        #pragma unroll 8
        for (int k = 0; k < HDIM; k++) a += Wpre[i * HDIM + k] * Wconv[k * HDIM + j];
        g_Wf[i * HDIM + j] = a;
    } else {
        float a = 0.f;
        #pragma unroll 8
        for (int k = 0; k < HDIM; k++) a += bpre[k] * Wconv[k * HDIM + j];
        g_bf[j] = a;
    }
}

// ---------------- main GEMM: h1 = x @ Wf + bf ------------------------------
// Block: 128 threads; tile BM=64 rows x BN=32 cols; thread microtile 4x4.
__global__ __launch_bounds__(128) void k_gemm(const float* __restrict__ x, int N) {
    __shared__ float xs[FDIM][64];   // transposed: xs[k][row]   (32 KB)
    __shared__ float Ws[FDIM][32];   // Ws[k][j]                 (16 KB)
    int tid = threadIdx.x;
    int rb = blockIdx.x;             // row tile
    int jb = blockIdx.y;             // col tile (0..3)
    int tj = tid & 7;                // 8 col-groups of 4
    int tr = tid >> 3;               // 16 row-groups of 4

    // load x tile (transposed into smem)
    {
        int row = tid >> 1;
        int ch  = (tid & 1) * 64;
        int grow = rb * 64 + row;
        const float* xr = x + (size_t)grow * FDIM;
        bool rv = grow < N;
        #pragma unroll
        for (int i = 0; i < 16; i++) {
            int c = ch + i * 4;
            float4 v = rv ? *(const float4*)&xr[c] : make_float4(0.f, 0.f, 0.f, 0.f);
            xs[c + 0][row] = v.x; xs[c + 1][row] = v.y;
            xs[c + 2][row] = v.z; xs[c + 3][row] = v.w;
        }
    }
    // load W tile
    #pragma unroll
    for (int i = 0; i < 8; i++) {
        int lin = tid * 4 + i * 512;
        int k = lin >> 5, j = lin & 31;
        *(float4*)&Ws[k][j] = *(const float4*)&g_Wf[k * HDIM + jb * 32 + j];
    }
    __syncthreads();

    float4 acc[4];
    #pragma unroll
    for (int r = 0; r < 4; r++) acc[r] = make_float4(0.f, 0.f, 0.f, 0.f);

    #pragma unroll 4
    for (int k = 0; k < FDIM; k++) {
        float4 w = *(float4*)&Ws[k][tj * 4];
        #pragma unroll
        for (int r = 0; r < 4; r++) {
            float xv = xs[k][tr * 4 + r];
            acc[r].x += xv * w.x; acc[r].y += xv * w.y;
            acc[r].z += xv * w.z; acc[r].w += xv * w.w;
        }
    }

    float4 bf4 = *(const float4*)&g_bf[jb * 32 + tj * 4];
    #pragma unroll
    for (int r = 0; r < 4; r++) {
        int row = rb * 64 + tr * 4 + r;
        if (row < N) {
            float4 o = make_float4(acc[r].x + bf4.x, acc[r].y + bf4.y,
                                   acc[r].z + bf4.z, acc[r].w + bf4.w);
            *(float4*)&g_h1[(size_t)row * HDIM + jb * 32 + tj * 4] = o;
        }
    }
}

// ---------------- degree count ---------------------------------------------
__global__ void k_count(const void* __restrict__ ei, int E) {
    bool w64 = g_is64 != 0;
    int i = blockIdx.x * blockDim.x + threadIdx.x;
    if (i >= E) return;
    int d = ld_idx(ei, (long long)E + i, w64);
    atomicAdd(&g_cnt[d], 1);
}

__global__ void k_dinv(int N) {
    int i = blockIdx.x * blockDim.x + threadIdx.x;
    if (i < N) g_dinv[i] = rsqrtf((float)(g_cnt[i] + 1));
}

// ---------------- exclusive scan of g_cnt -> g_rowptr ----------------------
__global__ void k_scan1(int N) {
    __shared__ int sm[1024];
    int i = blockIdx.x * 1024 + threadIdx.x;
    int v = (i < N) ? g_cnt[i] : 0;
    sm[threadIdx.x] = v;
    __syncthreads();
    for (int off = 1; off < 1024; off <<= 1) {
        int t = (threadIdx.x >= off) ? sm[threadIdx.x - off] : 0;
        __syncthreads();
        sm[threadIdx.x] += t;
        __syncthreads();
    }
    if (i < N) g_rowptr[i] = sm[threadIdx.x] - v;
    if (threadIdx.x == 1023) g_blocksums[blockIdx.x] = sm[1023];
}

__global__ void k_scan2(int NB) {
    __shared__ int sm[256];
    int t = threadIdx.x;
    int v = (t < NB) ? g_blocksums[t] : 0;
    sm[t] = v;
    __syncthreads();
    for (int off = 1; off < 256; off <<= 1) {
        int u = (t >= off) ? sm[t - off] : 0;
        __syncthreads();
        sm[t] += u;
        __syncthreads();
    }
    if (t < NB) g_blocksums[t] = sm[t] - v;
}

__global__ void k_scan3(int N) {
    int i = blockIdx.x * 1024 + threadIdx.x;
    if (i < N) g_rowptr[i] += g_blocksums[blockIdx.x];
}

// ---------------- CSR fill --------------------------------------------------
__global__ void k_fill(const void* __restrict__ ei, int E) {
    bool w64 = g_is64 != 0;
    int i = blockIdx.x * blockDim.x + threadIdx.x;
    if (i >= E) return;
    int s = ld_idx(ei, i, w64);
    int d = ld_idx(ei, (long long)E + i, w64);
    int pos = atomicAdd(&g_fill[d], 1);
    g_csr[g_rowptr[d] + pos] = s;
}

// ---------------- propagation + LayerNorm + ReLU + pooling ------------------
// One warp per node; 8 warps / block; batch is sorted so most blocks are
// single-graph -> smem partial sum, 8x fewer global atomics.
__global__ __launch_bounds__(256) void k_main(const void* __restrict__ batch,
                                              const float* __restrict__ b_conv,
                                              const float* __restrict__ gamma,
                                              const float* __restrict__ beta,
                                              int N) {
    const bool w64 = g_is64 != 0;
    int warp = threadIdx.x >> 5, lane = threadIdx.x & 31;
    int v = blockIdx.x * 8 + warp;
    __shared__ int   sgph[8];
    __shared__ float sacc[HDIM];
    __shared__ int   s_same;

    bool valid = v < N;
    float4 y = make_float4(0.f, 0.f, 0.f, 0.f);
    int g = -1;

    if (valid) {
        float dv = g_dinv[v];
        float4 acc;
        {
            float4 hv = *(const float4*)&g_h1[(size_t)v * HDIM + lane * 4];
            float sw = dv * dv;
            acc = make_float4(sw * hv.x, sw * hv.y, sw * hv.z, sw * hv.w);
        }
        int start = g_rowptr[v], cnt = g_cnt[v];
        for (int base = 0; base < cnt; base += 32) {
            int e = base + lane;
            int s = 0; float ww = 0.f;
            if (e < cnt) { s = g_csr[start + e]; ww = g_dinv[s] * dv; }
            int m = min(32, cnt - base);
            for (int j = 0; j < m; j++) {
                int   ss = __shfl_sync(0xffffffffu, s, j);
                float wj = __shfl_sync(0xffffffffu, ww, j);
                float4 hs = *(const float4*)&g_h1[(size_t)ss * HDIM + lane * 4];
                acc.x += wj * hs.x; acc.y += wj * hs.y;
                acc.z += wj * hs.z; acc.w += wj * hs.w;
            }
        }
        {
            float4 bc = *(const float4*)&b_conv[lane * 4];
            acc.x += bc.x; acc.y += bc.y; acc.z += bc.z; acc.w += bc.w;
        }
        // LayerNorm over 128 features (4 per lane)
        float sum = acc.x + acc.y + acc.z + acc.w;
        #pragma unroll
        for (int o = 16; o; o >>= 1) sum += __shfl_xor_sync(0xffffffffu, sum, o);
        float mu = sum * (1.f / 128.f);
        float cx = acc.x - mu, cy = acc.y - mu, cz = acc.z - mu, cw = acc.w - mu;
        float sq = cx * cx + cy * cy + cz * cz + cw * cw;
        #pragma unroll
        for (int o = 16; o; o >>= 1) sq += __shfl_xor_sync(0xffffffffu, sq, o);
        float inv = rsqrtf(sq * (1.f / 128.f) + 1e-5f);
        float4 ga = *(const float4*)&gamma[lane * 4];
        float4 be = *(const float4*)&beta[lane * 4];
        y.x = fmaxf(0.f, ga.x * cx * inv + be.x);
        y.y = fmaxf(0.f, ga.y * cy * inv + be.y);
        y.z = fmaxf(0.f, ga.z * cz * inv + be.z);
        y.w = fmaxf(0.f, ga.w * cw * inv + be.w);
        g = ld_idx(batch, v, w64);
    }

    sgph[warp] = valid ? g : -1;
    if (threadIdx.x < HDIM) sacc[threadIdx.x] = 0.f;
    __syncthreads();
    if (threadIdx.x == 0) {
        int g0 = -1; bool same = true;
        for (int i = 0; i < 8; i++) {
            int gi = sgph[i];
            if (gi >= 0) { if (g0 < 0) g0 = gi; else if (gi != g0) same = false; }
        }
        s_same = same ? g0 : -2;   // -2 = mixed graphs in block; g0 may be -1 (no valid)
    }
    __syncthreads();
    int smflag = s_same;
    if (valid) {
        if (smflag != -2) {
            atomicAdd(&sacc[lane * 4 + 0], y.x);
            atomicAdd(&sacc[lane * 4 + 1], y.y);
            atomicAdd(&sacc[lane * 4 + 2], y.z);
            atomicAdd(&sacc[lane * 4 + 3], y.w);
        } else {
            float* ro = &g_readout[(size_t)g * HDIM + lane * 4];
            atomicAdd(ro + 0, y.x); atomicAdd(ro + 1, y.y);
            atomicAdd(ro + 2, y.z); atomicAdd(ro + 3, y.w);
        }
    }
    __syncthreads();
    if (smflag >= 0 && threadIdx.x < HDIM)
        atomicAdd(&g_readout[(size_t)smflag * HDIM + threadIdx.x], sacc[threadIdx.x]);
}

// ---------------- epilogue GEMM: out = readout @ W_post + b_post ------------
__global__ void k_out(const float* __restrict__ Wp, const float* __restrict__ bp,
                      float* __restrict__ out) {
    __shared__ float r[HDIM];
    int b = blockIdx.x, j = threadIdx.x;   // 64 threads
    r[j]      = g_readout[(size_t)b * HDIM + j];
    r[j + 64] = g_readout[(size_t)b * HDIM + j + 64];
    __syncthreads();
    float acc = bp[j];
    #pragma unroll 8
    for (int k = 0; k < HDIM; k++) acc += r[k] * Wp[k * CDIM + j];
    out[b * CDIM + j] = acc;
}

// ---------------- launch ----------------------------------------------------
extern "C" void kernel_launch(void* const* d_in, const int* in_sizes, int n_in,
                              void* d_out, int out_size) {
    const float* x      = (const float*)d_in[0];
    const void*  ei     = d_in[1];
    const void*  batch  = d_in[2];
    const float* W_pre  = (const float*)d_in[3];
    const float* b_pre  = (const float*)d_in[4];
    const float* W_conv = (const float*)d_in[5];
    const float* b_conv = (const float*)d_in[6];
    const float* gamma  = (const float*)d_in[7];
    const float* beta   = (const float*)d_in[8];
    const float* W_post = (const float*)d_in[9];
    const float* b_post = (const float*)d_in[10];

    int N = in_sizes[0] / FDIM;
    int E = in_sizes[1] / 2;
    int G = out_size / CDIM;
    if (N > NMAX) N = NMAX;
    if (E > EMAX) E = EMAX;
    if (G > GMAX) G = GMAX;
    int NB = (N + 1023) / 1024;

    k_detect<<<1, 32>>>((const int*)ei);
    {
        int total = 2 * N + G * HDIM;
        k_zero<<<(total + 255) / 256, 256>>>(N, G);
    }
    k_fuse<<<FDIM + 1, HDIM>>>(W_pre, b_pre, W_conv);
    {
        dim3 grid((N + 63) / 64, 4);
        k_gemm<<<grid, 128>>>(x, N);
    }
    k_count<<<(E + 255) / 256, 256>>>(ei, E);
    k_dinv<<<(N + 255) / 256, 256>>>(N);
    k_scan1<<<NB, 1024>>>(N);
    k_scan2<<<1, 256>>>(NB);
    k_scan3<<<NB, 1024>>>(N);
    k_fill<<<(E + 255) / 256, 256>>>(ei, E);
    k_main<<<(N + 7) / 8, 256>>>(batch, b_conv, gamma, beta, N);
    k_out<<<G, CDIM>>>(W_post, b_post, (float*)d_out);
}

// round 3
// speedup vs baseline: 1.5134x; 1.5134x over previous
#include <cuda_runtime.h>
#include <cuda_bf16.h>
#include <stdint.h>

// Problem constants (fixed-shape problem; runtime sizes used for loop bounds)
#define NMAX 100000
#define EMAX 1600000
#define HDIM 128
#define FDIM 128
#define CDIM 64
#define GMAX 512

// ---------------- scratch (__device__ globals; no runtime allocation) ------
__device__ float g_h1[(size_t)NMAX * HDIM];   // 51.2 MB  node features after fused pre GEMM
__device__ float g_dinv[NMAX];
__device__ int   g_cnt[NMAX];                 // in-degree (edges only)
__device__ int   g_rowptr[NMAX];              // exclusive scan of g_cnt
__device__ int   g_fill[NMAX];
__device__ int   g_csr[EMAX];                 // src ids grouped by dst
__device__ int   g_blocksums[256];
__device__ float g_readout[GMAX * HDIM];
__device__ float g_Wf[FDIM * HDIM];           // W_pre @ W_conv
__device__ float g_bf[HDIM];                  // b_pre @ W_conv
__device__ int   g_is64;

__device__ __forceinline__ int ld_idx(const void* p, long long i, bool w64) {
    return w64 ? (int)((const long long*)p)[i] : ((const int*)p)[i];
}

// ---------------- zero scratch + index dtype detection ----------------------
// If edge_index is int64 (little-endian, values < 2^31), every odd 32-bit
// word of the buffer is 0. If int32, odd words are random indices.
__global__ void k_zero(const int* __restrict__ ei_words, int N, int G) {
    int i = blockIdx.x * blockDim.x + threadIdx.x;
    if (i == 0) {
        int acc = 0;
        for (int j = 1; j < 256; j += 2) acc |= ei_words[j];
        g_is64 = (acc == 0) ? 1 : 0;
    }
    int total = 2 * N + G * HDIM;
    if (i >= total) return;
    if (i < N)            g_cnt[i] = 0;
    else if (i < 2 * N)   g_fill[i - N] = 0;
    else                  g_readout[i - 2 * N] = 0.f;
}

// ---------------- fuse W_pre @ W_conv --------------------------------------
__global__ void k_fuse(const float* __restrict__ Wpre, const float* __restrict__ bpre,
                       const float* __restrict__ Wconv) {
    int j = threadIdx.x;           // 0..127
    int i = blockIdx.x;            // 0..128 (128 = bias row)
    if (i < FDIM) {
        float a = 0.f;
        #pragma unroll 8
        for (int k = 0; k < HDIM; k++) a += Wpre[i * HDIM + k] * Wconv[k * HDIM + j];
        g_Wf[i * HDIM + j] = a;
    } else {
        float a = 0.f;
        #pragma unroll 8
        for (int k = 0; k < HDIM; k++) a += bpre[k] * Wconv[k * HDIM + j];
        g_bf[j] = a;
    }
}

// ---------------- main GEMM: h1 = x @ Wf + bf  (tf32 mma.sync) --------------
// Block: 256 threads (8 warps, 2x4). Tile: 64 rows x 128 cols (full H).
// Whole Wf lives in smem (tf32-rounded). Per k-step a warp does 16 LDS.32
// feeding 8 HMMA m16n8k8 (16K FLOP).
#define XS_LD 132   // pad: A-frag bank = 4*g4 + t4 (+const)  -> 32 distinct
#define WS_LD 136   // pad: B-frag bank = 8*t4 + g4 (+const)  -> 32 distinct
#define GEMM_SMEM ((64 * XS_LD + 128 * WS_LD + 128) * 4)

__device__ __forceinline__ uint32_t f2tf32(float f) {
    uint32_t o;
    asm("cvt.rna.tf32.f32 %0, %1;" : "=r"(o) : "f"(f));
    return o;
}

__global__ __launch_bounds__(256) void k_gemm_mma(const float* __restrict__ x, int N) {
    extern __shared__ float smf[];
    float* xs  = smf;                       // [64][XS_LD]
    float* ws  = smf + 64 * XS_LD;          // [128][WS_LD]
    float* bfs = smf + 64 * XS_LD + 128 * WS_LD;  // [128]

    int tid  = threadIdx.x;
    int warp = tid >> 5, lane = tid & 31;
    int g4 = lane >> 2, t4 = lane & 3;      // groupID (0..7), tid-in-group (0..3)
    int wm = warp >> 2, wn = warp & 3;      // warp tile coords: 2 (m) x 4 (n)
    int rb = blockIdx.x * 64;

    // load Wf (128x128) -> ws, tf32-rounded
    #pragma unroll
    for (int i = 0; i < 16; i++) {
        int lin = tid + i * 256;            // float4 index
        int r = lin >> 5, c = (lin & 31) * 4;
        float4 v = *(const float4*)&g_Wf[r * HDIM + c];
        uint32_t* dst = (uint32_t*)&ws[r * WS_LD + c];
        dst[0] = f2tf32(v.x); dst[1] = f2tf32(v.y);
        dst[2] = f2tf32(v.z); dst[3] = f2tf32(v.w);
    }
    if (tid < HDIM) bfs[tid] = g_bf[tid];
    // load x tile (64x128) -> xs, tf32-rounded
    #pragma unroll
    for (int i = 0; i < 8; i++) {
        int lin = tid + i * 256;
        int r = lin >> 5, c = (lin & 31) * 4;
        int grow = rb + r;
        float4 v = (grow < N) ? *(const float4*)&x[(size_t)grow * FDIM + c]
                              : make_float4(0.f, 0.f, 0.f, 0.f);
        uint32_t* dst = (uint32_t*)&xs[r * XS_LD + c];
        dst[0] = f2tf32(v.x); dst[1] = f2tf32(v.y);
        dst[2] = f2tf32(v.z); dst[3] = f2tf32(v.w);
    }
    __syncthreads();

    float acc[2][4][4];
    #pragma unroll
    for (int mt = 0; mt < 2; mt++)
        #pragma unroll
        for (int nt = 0; nt < 4; nt++)
            #pragma unroll
            for (int q = 0; q < 4; q++) acc[mt][nt][q] = 0.f;

    #pragma unroll
    for (int ks = 0; ks < 16; ks++) {
        int k0 = ks * 8;
        uint32_t a[2][4];
        #pragma unroll
        for (int mt = 0; mt < 2; mt++) {
            int r0 = wm * 32 + mt * 16;
            a[mt][0] = __float_as_uint(xs[(r0 + g4    ) * XS_LD + k0 + t4    ]);
            a[mt][1] = __float_as_uint(xs[(r0 + g4 + 8) * XS_LD + k0 + t4    ]);
            a[mt][2] = __float_as_uint(xs[(r0 + g4    ) * XS_LD + k0 + t4 + 4]);
            a[mt][3] = __float_as_uint(xs[(r0 + g4 + 8) * XS_LD + k0 + t4 + 4]);
        }
        #pragma unroll
        for (int nt = 0; nt < 4; nt++) {
            int nb = wn * 32 + nt * 8 + g4;
            uint32_t b0 = __float_as_uint(ws[(k0 + t4    ) * WS_LD + nb]);
            uint32_t b1 = __float_as_uint(ws[(k0 + t4 + 4) * WS_LD + nb]);
            #pragma unroll
            for (int mt = 0; mt < 2; mt++) {
                asm volatile(
                    "mma.sync.aligned.m16n8k8.row.col.f32.tf32.tf32.f32 "
                    "{%0,%1,%2,%3}, {%4,%5,%6,%7}, {%8,%9}, {%0,%1,%2,%3};"
                    : "+f"(acc[mt][nt][0]), "+f"(acc[mt][nt][1]),
                      "+f"(acc[mt][nt][2]), "+f"(acc[mt][nt][3])
                    : "r"(a[mt][0]), "r"(a[mt][1]), "r"(a[mt][2]), "r"(a[mt][3]),
                      "r"(b0), "r"(b1));
            }
        }
    }

    // epilogue: + bias, store
    #pragma unroll
    for (int mt = 0; mt < 2; mt++) {
        int r0 = rb + wm * 32 + mt * 16 + g4;
        #pragma unroll
        for (int nt = 0; nt < 4; nt++) {
            int col = wn * 32 + nt * 8 + t4 * 2;
            float bv0 = bfs[col], bv1 = bfs[col + 1];
            if (r0 < N) {
                float2 o = make_float2(acc[mt][nt][0] + bv0, acc[mt][nt][1] + bv1);
                *(float2*)&g_h1[(size_t)r0 * HDIM + col] = o;
            }
            if (r0 + 8 < N) {
                float2 o = make_float2(acc[mt][nt][2] + bv0, acc[mt][nt][3] + bv1);
                *(float2*)&g_h1[(size_t)(r0 + 8) * HDIM + col] = o;
            }
        }
    }
}

// ---------------- degree count ---------------------------------------------
__global__ void k_count(const void* __restrict__ ei, int E) {
    bool w64 = g_is64 != 0;
    int i = blockIdx.x * blockDim.x + threadIdx.x;
    if (i >= E) return;
    int d = ld_idx(ei, (long long)E + i, w64);
    atomicAdd(&g_cnt[d], 1);
}

// ---------------- exclusive scan of g_cnt -> g_rowptr (+ dinv fused) -------
__global__ void k_scan1(int N) {
    __shared__ int sm[1024];
    int i = blockIdx.x * 1024 + threadIdx.x;
    int v = (i < N) ? g_cnt[i] : 0;
    if (i < N) g_dinv[i] = rsqrtf((float)(v + 1));
    sm[threadIdx.x] = v;
    __syncthreads();
    for (int off = 1; off < 1024; off <<= 1) {
        int t = (threadIdx.x >= off) ? sm[threadIdx.x - off] : 0;
        __syncthreads();
        sm[threadIdx.x] += t;
        __syncthreads();
    }
    if (i < N) g_rowptr[i] = sm[threadIdx.x] - v;
    if (threadIdx.x == 1023) g_blocksums[blockIdx.x] = sm[1023];
}

__global__ void k_scan2(int NB) {
    __shared__ int sm[256];
    int t = threadIdx.x;
    int v = (t < NB) ? g_blocksums[t] : 0;
    sm[t] = v;
    __syncthreads();
    for (int off = 1; off < 256; off <<= 1) {
        int u = (t >= off) ? sm[t - off] : 0;
        __syncthreads();
        sm[t] += u;
        __syncthreads();
    }
    if (t < NB) g_blocksums[t] = sm[t] - v;
}

__global__ void k_scan3(int N) {
    int i = blockIdx.x * 1024 + threadIdx.x;
    if (i < N) g_rowptr[i] += g_blocksums[blockIdx.x];
}

// ---------------- CSR fill --------------------------------------------------
__global__ void k_fill(const void* __restrict__ ei, int E) {
    bool w64 = g_is64 != 0;
    int i = blockIdx.x * blockDim.x + threadIdx.x;
    if (i >= E) return;
    int s = ld_idx(ei, i, w64);
    int d = ld_idx(ei, (long long)E + i, w64);
    int pos = atomicAdd(&g_fill[d], 1);
    g_csr[g_rowptr[d] + pos] = s;
}

// ---------------- propagation + LayerNorm + ReLU + pooling ------------------
// One warp per node; 8 warps / block; batch is sorted so most blocks are
// single-graph -> smem partial sum, 8x fewer global atomics.
__global__ __launch_bounds__(256) void k_main(const void* __restrict__ batch,
                                              const float* __restrict__ b_conv,
                                              const float* __restrict__ gamma,
                                              const float* __restrict__ beta,
                                              int N) {
    const bool w64 = g_is64 != 0;
    int warp = threadIdx.x >> 5, lane = threadIdx.x & 31;
    int v = blockIdx.x * 8 + warp;
    __shared__ int   sgph[8];
    __shared__ float sacc[HDIM];
    __shared__ int   s_same;

    bool valid = v < N;
    float4 y = make_float4(0.f, 0.f, 0.f, 0.f);
    int g = -1;

    if (valid) {
        float dv = g_dinv[v];
        float4 acc;
        {
            float4 hv = *(const float4*)&g_h1[(size_t)v * HDIM + lane * 4];
            float sw = dv * dv;
            acc = make_float4(sw * hv.x, sw * hv.y, sw * hv.z, sw * hv.w);
        }
        int start = g_rowptr[v], cnt = g_cnt[v];
        for (int base = 0; base < cnt; base += 32) {
            int e = base + lane;
            int s = 0; float ww = 0.f;
            if (e < cnt) { s = g_csr[start + e]; ww = g_dinv[s] * dv; }
            int m = min(32, cnt - base);
            for (int j = 0; j < m; j++) {
                int   ss = __shfl_sync(0xffffffffu, s, j);
                float wj = __shfl_sync(0xffffffffu, ww, j);
                float4 hs = *(const float4*)&g_h1[(size_t)ss * HDIM + lane * 4];
                acc.x += wj * hs.x; acc.y += wj * hs.y;
                acc.z += wj * hs.z; acc.w += wj * hs.w;
            }
        }
        {
            float4 bc = *(const float4*)&b_conv[lane * 4];
            acc.x += bc.x; acc.y += bc.y; acc.z += bc.z; acc.w += bc.w;
        }
        // LayerNorm over 128 features (4 per lane)
        float sum = acc.x + acc.y + acc.z + acc.w;
        #pragma unroll
        for (int o = 16; o; o >>= 1) sum += __shfl_xor_sync(0xffffffffu, sum, o);
        float mu = sum * (1.f / 128.f);
        float cx = acc.x - mu, cy = acc.y - mu, cz = acc.z - mu, cw = acc.w - mu;
        float sq = cx * cx + cy * cy + cz * cz + cw * cw;
        #pragma unroll
        for (int o = 16; o; o >>= 1) sq += __shfl_xor_sync(0xffffffffu, sq, o);
        float inv = rsqrtf(sq * (1.f / 128.f) + 1e-5f);
        float4 ga = *(const float4*)&gamma[lane * 4];
        float4 be = *(const float4*)&beta[lane * 4];
        y.x = fmaxf(0.f, ga.x * cx * inv + be.x);
        y.y = fmaxf(0.f, ga.y * cy * inv + be.y);
        y.z = fmaxf(0.f, ga.z * cz * inv + be.z);
        y.w = fmaxf(0.f, ga.w * cw * inv + be.w);
        g = ld_idx(batch, v, w64);
    }

    sgph[warp] = valid ? g : -1;
    if (threadIdx.x < HDIM) sacc[threadIdx.x] = 0.f;
    __syncthreads();
    if (threadIdx.x == 0) {
        int g0 = -1; bool same = true;
        for (int i = 0; i < 8; i++) {
            int gi = sgph[i];
            if (gi >= 0) { if (g0 < 0) g0 = gi; else if (gi != g0) same = false; }
        }
        s_same = same ? g0 : -2;   // -2 = mixed graphs in block; g0 may be -1 (no valid)
    }
    __syncthreads();
    int smflag = s_same;
    if (valid) {
        if (smflag != -2) {
            atomicAdd(&sacc[lane * 4 + 0], y.x);
            atomicAdd(&sacc[lane * 4 + 1], y.y);
            atomicAdd(&sacc[lane * 4 + 2], y.z);
            atomicAdd(&sacc[lane * 4 + 3], y.w);
        } else {
            float* ro = &g_readout[(size_t)g * HDIM + lane * 4];
            atomicAdd(ro + 0, y.x); atomicAdd(ro + 1, y.y);
            atomicAdd(ro + 2, y.z); atomicAdd(ro + 3, y.w);
        }
    }
    __syncthreads();
    if (smflag >= 0 && threadIdx.x < HDIM)
        atomicAdd(&g_readout[(size_t)smflag * HDIM + threadIdx.x], sacc[threadIdx.x]);
}

// ---------------- epilogue GEMM: out = readout @ W_post + b_post ------------
__global__ void k_out(const float* __restrict__ Wp, const float* __restrict__ bp,
                      float* __restrict__ out) {
    __shared__ float r[HDIM];
    int b = blockIdx.x, j = threadIdx.x;   // 64 threads
    r[j]      = g_readout[(size_t)b * HDIM + j];
    r[j + 64] = g_readout[(size_t)b * HDIM + j + 64];
    __syncthreads();
    float acc = bp[j];
    #pragma unroll 8
    for (int k = 0; k < HDIM; k++) acc += r[k] * Wp[k * CDIM + j];
    out[b * CDIM + j] = acc;
}

// ---------------- launch ----------------------------------------------------
extern "C" void kernel_launch(void* const* d_in, const int* in_sizes, int n_in,
                              void* d_out, int out_size) {
    const float* x      = (const float*)d_in[0];
    const void*  ei     = d_in[1];
    const void*  batch  = d_in[2];
    const float* W_pre  = (const float*)d_in[3];
    const float* b_pre  = (const float*)d_in[4];
    const float* W_conv = (const float*)d_in[5];
    const float* b_conv = (const float*)d_in[6];
    const float* gamma  = (const float*)d_in[7];
    const float* beta   = (const float*)d_in[8];
    const float* W_post = (const float*)d_in[9];
    const float* b_post = (const float*)d_in[10];

    int N = in_sizes[0] / FDIM;
    int E = in_sizes[1] / 2;
    int G = out_size / CDIM;
    if (N > NMAX) N = NMAX;
    if (E > EMAX) E = EMAX;
    if (G > GMAX) G = GMAX;
    int NB = (N + 1023) / 1024;

    cudaFuncSetAttribute(k_gemm_mma, cudaFuncAttributeMaxDynamicSharedMemorySize, GEMM_SMEM);

    {
        int total = 2 * N + G * HDIM;
        k_zero<<<(total + 255) / 256, 256>>>((const int*)ei, N, G);
    }
    k_fuse<<<FDIM + 1, HDIM>>>(W_pre, b_pre, W_conv);
    k_gemm_mma<<<(N + 63) / 64, 256, GEMM_SMEM>>>(x, N);
    k_count<<<(E + 255) / 256, 256>>>(ei, E);
    k_scan1<<<NB, 1024>>>(N);
    k_scan2<<<1, 256>>>(NB);
    k_scan3<<<NB, 1024>>>(N);
    k_fill<<<(E + 255) / 256, 256>>>(ei, E);
    k_main<<<(N + 7) / 8, 256>>>(batch, b_conv, gamma, beta, N);
    k_out<<<G, CDIM>>>(W_post, b_post, (float*)d_out);
}

// round 4
// speedup vs baseline: 1.6734x; 1.1057x over previous
#include <cuda_runtime.h>
#include <cuda_bf16.h>
#include <stdint.h>

// Problem constants (fixed-shape problem; runtime sizes used for loop bounds)
#define NMAX 100000
#define EMAX 1600000
#define HDIM 128
#define FDIM 128
#define CDIM 64
#define GMAX 512

// ---------------- scratch (__device__ globals; no runtime allocation) ------
__device__ __nv_bfloat16 g_h1b[(size_t)NMAX * HDIM];  // 25.6 MB node features (bf16)
__device__ float g_dinv[NMAX];
__device__ int   g_cnt[NMAX];                 // in-degree (edges only)
__device__ int   g_rowptr[NMAX];              // exclusive scan of g_cnt
__device__ int   g_pos[NMAX];                 // fill cursor (starts = rowptr)
__device__ int   g_csr[EMAX];                 // src ids grouped by dst
__device__ int   g_blocksums[256];
__device__ float g_readout[GMAX * HDIM];
__device__ float g_Wf[FDIM * HDIM];           // W_pre @ W_conv
__device__ float g_bf[HDIM];                  // b_pre @ W_conv
__device__ int   g_is64;

__device__ __forceinline__ int ld_idx(const void* p, long long i, bool w64) {
    return w64 ? (int)((const long long*)p)[i] : ((const int*)p)[i];
}

// ---------------- zero scratch + index dtype detection ----------------------
// If edge_index is int64 (little-endian, values < 2^31), every odd 32-bit
// word of the buffer is 0. If int32, odd words are random indices.
__global__ void k_zero(const int* __restrict__ ei_words, int N, int G) {
    int i = blockIdx.x * blockDim.x + threadIdx.x;
    if (i == 0) {
        int acc = 0;
        for (int j = 1; j < 256; j += 2) acc |= ei_words[j];
        g_is64 = (acc == 0) ? 1 : 0;
    }
    int total = N + G * HDIM;
    if (i >= total) return;
    if (i < N) g_cnt[i] = 0;
    else       g_readout[i - N] = 0.f;
}

// ---------------- fuse W_pre @ W_conv --------------------------------------
__global__ void k_fuse(const float* __restrict__ Wpre, const float* __restrict__ bpre,
                       const float* __restrict__ Wconv) {
    int j = threadIdx.x;           // 0..127
    int i = blockIdx.x;            // 0..128 (128 = bias row)
    if (i < FDIM) {
        float a = 0.f;
        #pragma unroll 8
        for (int k = 0; k < HDIM; k++) a += Wpre[i * HDIM + k] * Wconv[k * HDIM + j];
        g_Wf[i * HDIM + j] = a;
    } else {
        float a = 0.f;
        #pragma unroll 8
        for (int k = 0; k < HDIM; k++) a += bpre[k] * Wconv[k * HDIM + j];
        g_bf[j] = a;
    }
}

// ---------------- main GEMM: h1 = x @ Wf + bf  (tf32 mma.sync, bf16 out) ----
#define XS_LD 132   // pad: A-frag bank = 4*g4 + t4 (+const)  -> 32 distinct
#define WS_LD 136   // pad: B-frag bank = 8*t4 + g4 (+const)  -> 32 distinct
#define GEMM_SMEM ((64 * XS_LD + 128 * WS_LD + 128) * 4)

__device__ __forceinline__ uint32_t f2tf32(float f) {
    uint32_t o;
    asm("cvt.rna.tf32.f32 %0, %1;" : "=r"(o) : "f"(f));
    return o;
}

__global__ __launch_bounds__(256) void k_gemm_mma(const float* __restrict__ x, int N) {
    extern __shared__ float smf[];
    float* xs  = smf;                       // [64][XS_LD]
    float* ws  = smf + 64 * XS_LD;          // [128][WS_LD]
    float* bfs = smf + 64 * XS_LD + 128 * WS_LD;  // [128]

    int tid  = threadIdx.x;
    int warp = tid >> 5, lane = tid & 31;
    int g4 = lane >> 2, t4 = lane & 3;      // groupID (0..7), tid-in-group (0..3)
    int wm = warp >> 2, wn = warp & 3;      // warp tile coords: 2 (m) x 4 (n)
    int rb = blockIdx.x * 64;

    // load Wf (128x128) -> ws, tf32-rounded
    #pragma unroll
    for (int i = 0; i < 16; i++) {
        int lin = tid + i * 256;            // float4 index
        int r = lin >> 5, c = (lin & 31) * 4;
        float4 v = *(const float4*)&g_Wf[r * HDIM + c];
        uint32_t* dst = (uint32_t*)&ws[r * WS_LD + c];
        dst[0] = f2tf32(v.x); dst[1] = f2tf32(v.y);
        dst[2] = f2tf32(v.z); dst[3] = f2tf32(v.w);
    }
    if (tid < HDIM) bfs[tid] = g_bf[tid];
    // load x tile (64x128) -> xs, tf32-rounded
    #pragma unroll
    for (int i = 0; i < 8; i++) {
        int lin = tid + i * 256;
        int r = lin >> 5, c = (lin & 31) * 4;
        int grow = rb + r;
        float4 v = (grow < N) ? *(const float4*)&x[(size_t)grow * FDIM + c]
                              : make_float4(0.f, 0.f, 0.f, 0.f);
        uint32_t* dst = (uint32_t*)&xs[r * XS_LD + c];
        dst[0] = f2tf32(v.x); dst[1] = f2tf32(v.y);
        dst[2] = f2tf32(v.z); dst[3] = f2tf32(v.w);
    }
    __syncthreads();

    float acc[2][4][4];
    #pragma unroll
    for (int mt = 0; mt < 2; mt++)
        #pragma unroll
        for (int nt = 0; nt < 4; nt++)
            #pragma unroll
            for (int q = 0; q < 4; q++) acc[mt][nt][q] = 0.f;

    #pragma unroll
    for (int ks = 0; ks < 16; ks++) {
        int k0 = ks * 8;
        uint32_t a[2][4];
        #pragma unroll
        for (int mt = 0; mt < 2; mt++) {
            int r0 = wm * 32 + mt * 16;
            a[mt][0] = __float_as_uint(xs[(r0 + g4    ) * XS_LD + k0 + t4    ]);
            a[mt][1] = __float_as_uint(xs[(r0 + g4 + 8) * XS_LD + k0 + t4    ]);
            a[mt][2] = __float_as_uint(xs[(r0 + g4    ) * XS_LD + k0 + t4 + 4]);
            a[mt][3] = __float_as_uint(xs[(r0 + g4 + 8) * XS_LD + k0 + t4 + 4]);
        }
        #pragma unroll
        for (int nt = 0; nt < 4; nt++) {
            int nb = wn * 32 + nt * 8 + g4;
            uint32_t b0 = __float_as_uint(ws[(k0 + t4    ) * WS_LD + nb]);
            uint32_t b1 = __float_as_uint(ws[(k0 + t4 + 4) * WS_LD + nb]);
            #pragma unroll
            for (int mt = 0; mt < 2; mt++) {
                asm volatile(
                    "mma.sync.aligned.m16n8k8.row.col.f32.tf32.tf32.f32 "
                    "{%0,%1,%2,%3}, {%4,%5,%6,%7}, {%8,%9}, {%0,%1,%2,%3};"
                    : "+f"(acc[mt][nt][0]), "+f"(acc[mt][nt][1]),
                      "+f"(acc[mt][nt][2]), "+f"(acc[mt][nt][3])
                    : "r"(a[mt][0]), "r"(a[mt][1]), "r"(a[mt][2]), "r"(a[mt][3]),
                      "r"(b0), "r"(b1));
            }
        }
    }

    // epilogue: + bias, convert to bf16, store
    #pragma unroll
    for (int mt = 0; mt < 2; mt++) {
        int r0 = rb + wm * 32 + mt * 16 + g4;
        #pragma unroll
        for (int nt = 0; nt < 4; nt++) {
            int col = wn * 32 + nt * 8 + t4 * 2;
            float bv0 = bfs[col], bv1 = bfs[col + 1];
            if (r0 < N) {
                __nv_bfloat162 o = __float22bfloat162_rn(
                    make_float2(acc[mt][nt][0] + bv0, acc[mt][nt][1] + bv1));
                *(__nv_bfloat162*)&g_h1b[(size_t)r0 * HDIM + col] = o;
            }
            if (r0 + 8 < N) {
                __nv_bfloat162 o = __float22bfloat162_rn(
                    make_float2(acc[mt][nt][2] + bv0, acc[mt][nt][3] + bv1));
                *(__nv_bfloat162*)&g_h1b[(size_t)(r0 + 8) * HDIM + col] = o;
            }
        }
    }
}

// ---------------- degree count ---------------------------------------------
__global__ void k_count(const void* __restrict__ ei, int E) {
    bool w64 = g_is64 != 0;
    int i = blockIdx.x * blockDim.x + threadIdx.x;
    if (i >= E) return;
    int d = ld_idx(ei, (long long)E + i, w64);
    atomicAdd(&g_cnt[d], 1);
}

// ---------------- exclusive scan of g_cnt -> g_rowptr (+ dinv fused) -------
__global__ void k_scan1(int N) {
    __shared__ int sm[1024];
    int i = blockIdx.x * 1024 + threadIdx.x;
    int v = (i < N) ? g_cnt[i] : 0;
    if (i < N) g_dinv[i] = rsqrtf((float)(v + 1));
    sm[threadIdx.x] = v;
    __syncthreads();
    for (int off = 1; off < 1024; off <<= 1) {
        int t = (threadIdx.x >= off) ? sm[threadIdx.x - off] : 0;
        __syncthreads();
        sm[threadIdx.x] += t;
        __syncthreads();
    }
    if (i < N) g_rowptr[i] = sm[threadIdx.x] - v;
    if (threadIdx.x == 1023) g_blocksums[blockIdx.x] = sm[1023];
}

__global__ void k_scan2(int NB) {
    __shared__ int sm[256];
    int t = threadIdx.x;
    int v = (t < NB) ? g_blocksums[t] : 0;
    sm[t] = v;
    __syncthreads();
    for (int off = 1; off < 256; off <<= 1) {
        int u = (t >= off) ? sm[t - off] : 0;
        __syncthreads();
        sm[t] += u;
        __syncthreads();
    }
    if (t < NB) g_blocksums[t] = sm[t] - v;
}

__global__ void k_scan3(int N) {
    int i = blockIdx.x * 1024 + threadIdx.x;
    if (i < N) {
        int r = g_rowptr[i] + g_blocksums[blockIdx.x];
        g_rowptr[i] = r;
        g_pos[i] = r;
    }
}

// ---------------- CSR fill --------------------------------------------------
__global__ void k_fill(const void* __restrict__ ei, int E) {
    bool w64 = g_is64 != 0;
    int i = blockIdx.x * blockDim.x + threadIdx.x;
    if (i >= E) return;
    int s = ld_idx(ei, i, w64);
    int d = ld_idx(ei, (long long)E + i, w64);
    int pos = atomicAdd(&g_pos[d], 1);
    g_csr[pos] = s;
}

// ---------------- propagation + LayerNorm + ReLU + pooling ------------------
// One warp per node; 8 warps / block; batch is sorted so most blocks are
// single-graph -> smem partial sum, 8x fewer global atomics.
__device__ __forceinline__ float4 bf16x4_to_f4(uint2 raw) {
    __nv_bfloat162 lo = *(__nv_bfloat162*)&raw.x;
    __nv_bfloat162 hi = *(__nv_bfloat162*)&raw.y;
    float2 a = __bfloat1622float2(lo);
    float2 b = __bfloat1622float2(hi);
    return make_float4(a.x, a.y, b.x, b.y);
}

__global__ __launch_bounds__(256) void k_main(const void* __restrict__ batch,
                                              const float* __restrict__ b_conv,
                                              const float* __restrict__ gamma,
                                              const float* __restrict__ beta,
                                              int N) {
    const bool w64 = g_is64 != 0;
    int warp = threadIdx.x >> 5, lane = threadIdx.x & 31;
    int v = blockIdx.x * 8 + warp;
    __shared__ int   sgph[8];
    __shared__ float sacc[HDIM];
    __shared__ int   s_same;

    bool valid = v < N;
    float4 y = make_float4(0.f, 0.f, 0.f, 0.f);
    int g = -1;

    if (valid) {
        float dv = g_dinv[v];
        float4 acc;
        {
            uint2 raw = *(const uint2*)&g_h1b[(size_t)v * HDIM + lane * 4];
            float4 hv = bf16x4_to_f4(raw);
            float sw = dv * dv;
            acc = make_float4(sw * hv.x, sw * hv.y, sw * hv.z, sw * hv.w);
        }
        int start = g_rowptr[v], cnt = g_cnt[v];
        for (int base = 0; base < cnt; base += 32) {
            int e = base + lane;
            int s = 0; float ww = 0.f;
            if (e < cnt) { s = g_csr[start + e]; ww = g_dinv[s] * dv; }
            int m = min(32, cnt - base);
            #pragma unroll 4
            for (int j = 0; j < m; j++) {
                int   ss = __shfl_sync(0xffffffffu, s, j);
                float wj = __shfl_sync(0xffffffffu, ww, j);
                uint2 raw = *(const uint2*)&g_h1b[(size_t)ss * HDIM + lane * 4];
                float4 hs = bf16x4_to_f4(raw);
                acc.x += wj * hs.x; acc.y += wj * hs.y;
                acc.z += wj * hs.z; acc.w += wj * hs.w;
            }
        }
        {
            float4 bc = *(const float4*)&b_conv[lane * 4];
            acc.x += bc.x; acc.y += bc.y; acc.z += bc.z; acc.w += bc.w;
        }
        // LayerNorm over 128 features (4 per lane)
        float sum = acc.x + acc.y + acc.z + acc.w;
        #pragma unroll
        for (int o = 16; o; o >>= 1) sum += __shfl_xor_sync(0xffffffffu, sum, o);
        float mu = sum * (1.f / 128.f);
        float cx = acc.x - mu, cy = acc.y - mu, cz = acc.z - mu, cw = acc.w - mu;
        float sq = cx * cx + cy * cy + cz * cz + cw * cw;
        #pragma unroll
        for (int o = 16; o; o >>= 1) sq += __shfl_xor_sync(0xffffffffu, sq, o);
        float inv = rsqrtf(sq * (1.f / 128.f) + 1e-5f);
        float4 ga = *(const float4*)&gamma[lane * 4];
        float4 be = *(const float4*)&beta[lane * 4];
        y.x = fmaxf(0.f, ga.x * cx * inv + be.x);
        y.y = fmaxf(0.f, ga.y * cy * inv + be.y);
        y.z = fmaxf(0.f, ga.z * cz * inv + be.z);
        y.w = fmaxf(0.f, ga.w * cw * inv + be.w);
        g = ld_idx(batch, v, w64);
    }

    sgph[warp] = valid ? g : -1;
    if (threadIdx.x < HDIM) sacc[threadIdx.x] = 0.f;
    __syncthreads();
    if (threadIdx.x == 0) {
        int g0 = -1; bool same = true;
        for (int i = 0; i < 8; i++) {
            int gi = sgph[i];
            if (gi >= 0) { if (g0 < 0) g0 = gi; else if (gi != g0) same = false; }
        }
        s_same = same ? g0 : -2;   // -2 = mixed graphs in block; g0 may be -1 (no valid)
    }
    __syncthreads();
    int smflag = s_same;
    if (valid) {
        if (smflag != -2) {
            atomicAdd(&sacc[lane * 4 + 0], y.x);
            atomicAdd(&sacc[lane * 4 + 1], y.y);
            atomicAdd(&sacc[lane * 4 + 2], y.z);
            atomicAdd(&sacc[lane * 4 + 3], y.w);
        } else {
            float* ro = &g_readout[(size_t)g * HDIM + lane * 4];
            atomicAdd(ro + 0, y.x); atomicAdd(ro + 1, y.y);
            atomicAdd(ro + 2, y.z); atomicAdd(ro + 3, y.w);
        }
    }
    __syncthreads();
    if (smflag >= 0 && threadIdx.x < HDIM)
        atomicAdd(&g_readout[(size_t)smflag * HDIM + threadIdx.x], sacc[threadIdx.x]);
}

// ---------------- epilogue GEMM: out = readout @ W_post + b_post ------------
__global__ void k_out(const float* __restrict__ Wp, const float* __restrict__ bp,
                      float* __restrict__ out) {
    __shared__ float r[HDIM];
    int b = blockIdx.x, j = threadIdx.x;   // 64 threads
    r[j]      = g_readout[(size_t)b * HDIM + j];
    r[j + 64] = g_readout[(size_t)b * HDIM + j + 64];
    __syncthreads();
    float acc = bp[j];
    #pragma unroll 8
    for (int k = 0; k < HDIM; k++) acc += r[k] * Wp[k * CDIM + j];
    out[b * CDIM + j] = acc;
}

// ---------------- launch ----------------------------------------------------
extern "C" void kernel_launch(void* const* d_in, const int* in_sizes, int n_in,
                              void* d_out, int out_size) {
    const float* x      = (const float*)d_in[0];
    const void*  ei     = d_in[1];
    const void*  batch  = d_in[2];
    const float* W_pre  = (const float*)d_in[3];
    const float* b_pre  = (const float*)d_in[4];
    const float* W_conv = (const float*)d_in[5];
    const float* b_conv = (const float*)d_in[6];
    const float* gamma  = (const float*)d_in[7];
    const float* beta   = (const float*)d_in[8];
    const float* W_post = (const float*)d_in[9];
    const float* b_post = (const float*)d_in[10];

    int N = in_sizes[0] / FDIM;
    int E = in_sizes[1] / 2;
    int G = out_size / CDIM;
    if (N > NMAX) N = NMAX;
    if (E > EMAX) E = EMAX;
    if (G > GMAX) G = GMAX;
    int NB = (N + 1023) / 1024;

    cudaFuncSetAttribute(k_gemm_mma, cudaFuncAttributeMaxDynamicSharedMemorySize, GEMM_SMEM);

    {
        int total = N + G * HDIM;
        k_zero<<<(total + 255) / 256, 256>>>((const int*)ei, N, G);
    }
    k_fuse<<<FDIM + 1, HDIM>>>(W_pre, b_pre, W_conv);
    k_gemm_mma<<<(N + 63) / 64, 256, GEMM_SMEM>>>(x, N);
    k_count<<<(E + 255) / 256, 256>>>(ei, E);
    k_scan1<<<NB, 1024>>>(N);
    k_scan2<<<1, 256>>>(NB);
    k_scan3<<<NB, 1024>>>(N);
    k_fill<<<(E + 255) / 256, 256>>>(ei, E);
    k_main<<<(N + 7) / 8, 256>>>(batch, b_conv, gamma, beta, N);
    k_out<<<G, CDIM>>>(W_post, b_post, (float*)d_out);
}